// round 2
// baseline (speedup 1.0000x reference)
#include <cuda_runtime.h>
#include <math.h>
#include <stdint.h>

#define NLR  50000
#define EMBD 128
#define ENUM 800000

// ---------------- device scratch (no allocations allowed) ----------------
__device__ float g_logits[(size_t)ENUM * 4];
__device__ float g_xl[(size_t)NLR * EMBD];
__device__ float g_xr[(size_t)NLR * EMBD];
__device__ float g_ln[(size_t)NLR * EMBD];
__device__ float g_h1[(size_t)NLR * EMBD];
__device__ int   g_cnt[NLR];
__device__ int   g_off[NLR + 1];
__device__ int   g_cur[NLR];
__device__ int   g_elist[ENUM];

// ---------------- helpers ----------------
__device__ __forceinline__ uint32_t f2tf(float f) {
    uint32_t u;
    asm("cvt.rna.tf32.f32 %0, %1;" : "=r"(u) : "f"(f));
    return u;
}

__device__ __forceinline__ void mma8(float c[4], const uint32_t a[4], const uint32_t b[2]) {
    asm volatile(
        "mma.sync.aligned.m16n8k8.row.col.f32.tf32.tf32.f32 "
        "{%0,%1,%2,%3},{%4,%5,%6,%7},{%8,%9},{%0,%1,%2,%3};\n"
        : "+f"(c[0]), "+f"(c[1]), "+f"(c[2]), "+f"(c[3])
        : "r"(a[0]), "r"(a[1]), "r"(a[2]), "r"(a[3]), "r"(b[0]), "r"(b[1]));
}

// =================================================================
// Generic tf32 GEMM: C[M,128] = act( A1[M,K1]@B1 + A2[M,K2]@B2 + bias )
// Block tile 128x128, 8 warps in 4x2 grid (warp tile 32x64), K chunks of 32.
// =================================================================
__global__ __launch_bounds__(256) void gemm128(
    const float* __restrict__ A1, const float* __restrict__ B1, int K1,
    const float* __restrict__ A2, const float* __restrict__ B2, int K2,
    const float* __restrict__ bias, float* __restrict__ C, int M, int doRelu)
{
    __shared__ uint32_t As[128][36];
    __shared__ uint32_t Bs[32][136];
    __shared__ float    bias_s[128];

    const int tid = threadIdx.x;
    const int m0  = blockIdx.x * 128;
    if (tid < 128) bias_s[tid] = bias[tid];

    const int warp = tid >> 5, lane = tid & 31;
    const int wm = warp & 3, wn = warp >> 2;
    const int grp = lane >> 2, tg = lane & 3;

    float acc[2][8][4];
#pragma unroll
    for (int a = 0; a < 2; a++)
#pragma unroll
        for (int b = 0; b < 8; b++)
#pragma unroll
            for (int k = 0; k < 4; k++) acc[a][b][k] = 0.f;

    const int nch1 = K1 >> 5;
    const int nch  = nch1 + (K2 >> 5);

    for (int c = 0; c < nch; c++) {
        const float *A, *B; int K, kk;
        if (c < nch1) { A = A1; B = B1; K = K1; kk = c * 32; }
        else          { A = A2; B = B2; K = K2; kk = (c - nch1) * 32; }
        __syncthreads();
#pragma unroll
        for (int i = 0; i < 4; i++) {
            int slot = tid + i * 256;
            int r = slot >> 3, c4 = slot & 7;
            int grow = m0 + r;
            float4 a = (grow < M) ? *(const float4*)(A + (size_t)grow * K + kk + c4 * 4)
                                  : make_float4(0.f, 0.f, 0.f, 0.f);
            *(uint4*)&As[r][c4 * 4] = make_uint4(f2tf(a.x), f2tf(a.y), f2tf(a.z), f2tf(a.w));
            int rb = slot >> 5, cb = slot & 31;
            float4 b = *(const float4*)(B + (size_t)(kk + rb) * 128 + cb * 4);
            *(uint4*)&Bs[rb][cb * 4] = make_uint4(f2tf(b.x), f2tf(b.y), f2tf(b.z), f2tf(b.w));
        }
        __syncthreads();

#pragma unroll
        for (int ks = 0; ks < 4; ks++) {
            const int kb = ks * 8;
            uint32_t af[2][4];
#pragma unroll
            for (int mt = 0; mt < 2; mt++) {
                int r0 = wm * 32 + mt * 16 + grp;
                af[mt][0] = As[r0][kb + tg];     af[mt][1] = As[r0 + 8][kb + tg];
                af[mt][2] = As[r0][kb + tg + 4]; af[mt][3] = As[r0 + 8][kb + tg + 4];
            }
#pragma unroll
            for (int nt = 0; nt < 8; nt++) {
                int cc = wn * 64 + nt * 8 + grp;
                uint32_t bf[2];
                bf[0] = Bs[kb + tg][cc];
                bf[1] = Bs[kb + tg + 4][cc];
#pragma unroll
                for (int mt = 0; mt < 2; mt++) mma8(acc[mt][nt], af[mt], bf);
            }
        }
    }

#pragma unroll
    for (int mt = 0; mt < 2; mt++) {
#pragma unroll
        for (int half = 0; half < 2; half++) {
            int grow = m0 + wm * 32 + mt * 16 + half * 8 + grp;
            if (grow < M) {
#pragma unroll
                for (int nt = 0; nt < 8; nt++) {
                    int cc = wn * 64 + nt * 8 + tg * 2;
                    float v0 = acc[mt][nt][half * 2 + 0] + bias_s[cc];
                    float v1 = acc[mt][nt][half * 2 + 1] + bias_s[cc + 1];
                    if (doRelu) { v0 = fmaxf(v0, 0.f); v1 = fmaxf(v1, 0.f); }
                    float2 o; o.x = v0; o.y = v1;
                    *(float2*)(C + (size_t)grow * 128 + cc) = o;
                }
            }
        }
    }
}

// =================================================================
// Fused edge kernel: eproj = EF @ W_e (tf32 mma, never materialized),
// z = leakyrelu(eproj + x_l[src] + x_r[dst], 0.2),
// logits[e,h] = z_h . att_h  -> g_logits[E][4]
// =================================================================
__global__ __launch_bounds__(256) void edge_logits_kernel(
    const float* __restrict__ EF, const float* __restrict__ We,
    const int* __restrict__ src, const int* __restrict__ dst,
    const float* __restrict__ att)
{
    __shared__ uint32_t As[128][36];
    __shared__ uint32_t Bs[32][136];
    __shared__ int   src_s[128], dst_s[128];
    __shared__ float att_s[128];

    const int tid = threadIdx.x;
    const int e0  = blockIdx.x * 128;
    if (tid < 128) { src_s[tid] = src[e0 + tid]; dst_s[tid] = dst[e0 + tid]; att_s[tid] = att[tid]; }

    const int warp = tid >> 5, lane = tid & 31;
    const int wm = warp & 3, wn = warp >> 2;
    const int grp = lane >> 2, tg = lane & 3;

    float acc[2][8][4];
#pragma unroll
    for (int a = 0; a < 2; a++)
#pragma unroll
        for (int b = 0; b < 8; b++)
#pragma unroll
            for (int k = 0; k < 4; k++) acc[a][b][k] = 0.f;

    for (int c = 0; c < 4; c++) {
        const int kk = c * 32;
        __syncthreads();
#pragma unroll
        for (int i = 0; i < 4; i++) {
            int slot = tid + i * 256;
            int r = slot >> 3, c4 = slot & 7;
            float4 a = *(const float4*)(EF + (size_t)(e0 + r) * 128 + kk + c4 * 4);
            *(uint4*)&As[r][c4 * 4] = make_uint4(f2tf(a.x), f2tf(a.y), f2tf(a.z), f2tf(a.w));
            int rb = slot >> 5, cb = slot & 31;
            float4 b = *(const float4*)(We + (size_t)(kk + rb) * 128 + cb * 4);
            *(uint4*)&Bs[rb][cb * 4] = make_uint4(f2tf(b.x), f2tf(b.y), f2tf(b.z), f2tf(b.w));
        }
        __syncthreads();

#pragma unroll
        for (int ks = 0; ks < 4; ks++) {
            const int kb = ks * 8;
            uint32_t af[2][4];
#pragma unroll
            for (int mt = 0; mt < 2; mt++) {
                int r0 = wm * 32 + mt * 16 + grp;
                af[mt][0] = As[r0][kb + tg];     af[mt][1] = As[r0 + 8][kb + tg];
                af[mt][2] = As[r0][kb + tg + 4]; af[mt][3] = As[r0 + 8][kb + tg + 4];
            }
#pragma unroll
            for (int nt = 0; nt < 8; nt++) {
                int cc = wn * 64 + nt * 8 + grp;
                uint32_t bf[2];
                bf[0] = Bs[kb + tg][cc];
                bf[1] = Bs[kb + tg + 4][cc];
#pragma unroll
                for (int mt = 0; mt < 2; mt++) mma8(acc[mt][nt], af[mt], bf);
            }
        }
    }

    // epilogue: gather x_l[src], x_r[dst], leaky-relu, att-dot, quad reduce
#pragma unroll
    for (int mt = 0; mt < 2; mt++) {
#pragma unroll
        for (int half = 0; half < 2; half++) {
            int row = wm * 32 + mt * 16 + half * 8 + grp;
            const float* xl = g_xl + (size_t)src_s[row] * 128;
            const float* xr = g_xr + (size_t)dst_s[row] * 128;
#pragma unroll
            for (int hh = 0; hh < 2; hh++) {
                float partial = 0.f;
#pragma unroll
                for (int ntl = 0; ntl < 4; ntl++) {
                    int nt = hh * 4 + ntl;
                    int col = wn * 64 + nt * 8 + tg * 2;
                    float2 a = *(const float2*)(xl + col);
                    float2 b = *(const float2*)(xr + col);
                    float z0 = acc[mt][nt][half * 2 + 0] + a.x + b.x;
                    float z1 = acc[mt][nt][half * 2 + 1] + a.y + b.y;
                    z0 = (z0 > 0.f) ? z0 : 0.2f * z0;
                    z1 = (z1 > 0.f) ? z1 : 0.2f * z1;
                    partial += z0 * att_s[col] + z1 * att_s[col + 1];
                }
                partial += __shfl_xor_sync(0xFFFFFFFFu, partial, 1);
                partial += __shfl_xor_sync(0xFFFFFFFFu, partial, 2);
                if (tg == 0)
                    g_logits[(size_t)(e0 + row) * 4 + wn * 2 + hh] = partial;
            }
        }
    }
}

// ---------------- CSR build ----------------
__global__ void zero_cnt_kernel() {
    int i = blockIdx.x * blockDim.x + threadIdx.x;
    if (i < NLR) g_cnt[i] = 0;
}

__global__ void count_kernel(const int* __restrict__ dst) {
    int e = blockIdx.x * blockDim.x + threadIdx.x;
    if (e < ENUM) atomicAdd(&g_cnt[dst[e]], 1);
}

__global__ __launch_bounds__(1024) void scan_kernel() {
    __shared__ int part[1024];
    const int t = threadIdx.x;
    const int CH = (NLR + 1023) / 1024;
    int start = t * CH, end = min(start + CH, NLR);
    int s = 0;
    for (int i = start; i < end; i++) s += g_cnt[i];
    part[t] = s;
    __syncthreads();
    for (int off = 1; off < 1024; off <<= 1) {
        int v = (t >= off) ? part[t - off] : 0;
        __syncthreads();
        part[t] += v;
        __syncthreads();
    }
    int run = part[t] - s;
    for (int i = start; i < end; i++) {
        g_off[i] = run; g_cur[i] = run;
        run += g_cnt[i];
    }
    if (t == 1023) g_off[NLR] = part[1023];
}

__global__ void fill_kernel(const int* __restrict__ dst) {
    int e = blockIdx.x * blockDim.x + threadIdx.x;
    if (e < ENUM) {
        int p = atomicAdd(&g_cur[dst[e]], 1);
        g_elist[p] = e;
    }
}

// =================================================================
// Fused segment softmax + message + b_conv + LayerNorm. 1 block / dst node.
// =================================================================
__global__ __launch_bounds__(128) void message_ln_kernel(
    const int* __restrict__ src,
    const float* __restrict__ bconv,
    const float* __restrict__ lng, const float* __restrict__ lnb)
{
    const int node = blockIdx.x;
    const int tid = threadIdx.x;
    const int w = tid >> 5, lane = tid & 31;
    const int off0 = g_off[node];
    const int deg  = g_off[node + 1] - off0;

    __shared__ float m_s[4], s_s[4], sv[4], sv2[4];

    // online softmax stats, head w per warp
    float m = -1e30f, s = 0.f;
    for (int i = lane; i < deg; i += 32) {
        int e = g_elist[off0 + i];
        float lg = g_logits[(size_t)e * 4 + w];
        if (lg > m) { s *= expf(m - lg); m = lg; }
        s += expf(lg - m);
    }
#pragma unroll
    for (int o = 16; o; o >>= 1) {
        float om = __shfl_xor_sync(0xFFFFFFFFu, m, o);
        float os = __shfl_xor_sync(0xFFFFFFFFu, s, o);
        float nm = fmaxf(m, om);
        s = s * expf(m - nm) + os * expf(om - nm);
        m = nm;
    }
    if (lane == 0) { m_s[w] = m; s_s[w] = s; }
    __syncthreads();

    const int c = tid, h = w;
    const float mh = m_s[h];
    const float inv = 1.f / (s_s[h] + 1e-16f);
    float acc = 0.f;
    for (int i = 0; i < deg; i++) {
        int e = g_elist[off0 + i];
        float a = expf(g_logits[(size_t)e * 4 + h] - mh) * inv;
        acc = fmaf(a, g_xl[(size_t)src[e] * 128 + c], acc);
    }
    float msg = acc + bconv[c];

    // LayerNorm over 128 channels
    float v = msg, v2 = msg * msg;
#pragma unroll
    for (int o = 16; o; o >>= 1) {
        v  += __shfl_xor_sync(0xFFFFFFFFu, v,  o);
        v2 += __shfl_xor_sync(0xFFFFFFFFu, v2, o);
    }
    if (lane == 0) { sv[w] = v; sv2[w] = v2; }
    __syncthreads();
    float S  = sv[0] + sv[1] + sv[2] + sv[3];
    float S2 = sv2[0] + sv2[1] + sv2[2] + sv2[3];
    float mu  = S * (1.f / 128.f);
    float var = fmaxf(S2 * (1.f / 128.f) - mu * mu, 0.f);
    float r = rsqrtf(var + 1e-5f);
    g_ln[(size_t)node * 128 + c] = (msg - mu) * r * lng[c] + lnb[c];
}

// =================================================================
extern "C" void kernel_launch(void* const* d_in, const int* in_sizes, int n_in,
                              void* d_out, int out_size) {
    const float* left  = (const float*)d_in[0];
    const int*   eidx  = (const int*)d_in[1];
    const float* ef    = (const float*)d_in[2];
    const float* right = (const float*)d_in[3];
    const float* W_l   = (const float*)d_in[4];
    const float* b_l   = (const float*)d_in[5];
    const float* W_r   = (const float*)d_in[6];
    const float* b_r   = (const float*)d_in[7];
    const float* W_e   = (const float*)d_in[8];
    const float* att   = (const float*)d_in[9];
    const float* bconv = (const float*)d_in[10];
    const float* ln_g  = (const float*)d_in[11];
    const float* ln_b  = (const float*)d_in[12];
    const float* W1    = (const float*)d_in[13];
    const float* b1    = (const float*)d_in[14];
    const float* W2    = (const float*)d_in[15];
    const float* b2    = (const float*)d_in[16];
    float* out = (float*)d_out;

    const int* src = eidx;
    const int* dst = eidx + ENUM;

    float* xl; cudaGetSymbolAddress((void**)&xl, g_xl);
    float* xr; cudaGetSymbolAddress((void**)&xr, g_xr);
    float* ln; cudaGetSymbolAddress((void**)&ln, g_ln);
    float* h1; cudaGetSymbolAddress((void**)&h1, g_h1);

    const int gblk = (NLR + 127) / 128;   // 391

    // node projections
    gemm128<<<gblk, 256>>>(left,  W_l, 128, nullptr, nullptr, 0, b_l, xl, NLR, 0);
    gemm128<<<gblk, 256>>>(right, W_r, 128, nullptr, nullptr, 0, b_r, xr, NLR, 0);

    // edge logits (fused GEMM + gather + leakyrelu + att dot)
    edge_logits_kernel<<<ENUM / 128, 256>>>(ef, W_e, src, dst, att);

    // CSR build
    zero_cnt_kernel<<<(NLR + 255) / 256, 256>>>();
    count_kernel<<<(ENUM + 255) / 256, 256>>>(dst);
    scan_kernel<<<1, 1024>>>();
    fill_kernel<<<(ENUM + 255) / 256, 256>>>(dst);

    // segment softmax + message + LN
    message_ln_kernel<<<NLR, 128>>>(src, bconv, ln_g, ln_b);

    // out MLP: h1 = relu([ln, right] @ W1 + b1); out = h1 @ W2 + b2
    gemm128<<<gblk, 256>>>(ln, W1, 128, right, W1 + 128 * 128, 128, b1, h1, NLR, 1);
    gemm128<<<gblk, 256>>>(h1, W2, 128, nullptr, nullptr, 0, b2, out, NLR, 0);
}